// round 3
// baseline (speedup 1.0000x reference)
#include <cuda_runtime.h>
#include <cuda_bf16.h>
#include <math.h>
#include <stdint.h>

// ---------------------------------------------------------------------------
// Problem constants
// ---------------------------------------------------------------------------
#define NW 1000   // words
#define ND 100    // docs
#define NF 100    // feature dim
#define TIw 512
#define HDw 128

#define NBLK 148
#define NT 512
#define TOTALTHR (NBLK * NT)

// Output layout (concatenated f32)
#define OFF_LAM   0
#define OFF_ZMAT  100
#define OFF_BETA  1000100
#define OFF_GAMMA 1001100
#define OFF_ETA   1001200
#define OFF_ZEV   1001300
#define OFF_H     101001300

// ---------------------------------------------------------------------------
// Device scratch (single-assignment per stage -> no stale-L1 hazards)
// ---------------------------------------------------------------------------
__device__ float g_T1[NW * NF];
__device__ float g_H1[NW * NF];
__device__ float g_T2[NW * NF];
__device__ float g_E1[NW * NF];
__device__ float g_heli[NW * NF];
__device__ float g_y[NW];
__device__ float g_wp[NF];
__device__ float g_kc[ND];
__device__ float g_norminv;

#define CSR_CAP 96
__device__ int   g_ccnt[NW];
__device__ int   g_ccol[NW * CSR_CAP];
__device__ float g_cval[NW * CSR_CAP];

// grid barrier state
__device__ unsigned g_barcnt = 0;
__device__ volatile unsigned g_bargen = 0;

__device__ __forceinline__ void gridbar() {
    __syncthreads();
    if (threadIdx.x == 0) {
        __threadfence();
        unsigned g = g_bargen;
        if (atomicAdd(&g_barcnt, 1u) == NBLK - 1) {
            g_barcnt = 0;
            __threadfence();
            g_bargen = g + 1;
        } else {
            while (g_bargen == g) { }
        }
    }
    __syncthreads();
}

__device__ __forceinline__ float warp_sum(float v) {
#pragma unroll
    for (int o = 16; o; o >>= 1) v += __shfl_xor_sync(0xffffffffu, v, o);
    return v;
}

__device__ __forceinline__ float load_scalar(const void* p) {
    int v = *(const int*)p;
    if (v >= 0 && v <= 1000000) return (float)v;
    return *(const float*)p;
}

// ---------------------------------------------------------------------------
// Side stream + events (static init; not during capture)
// ---------------------------------------------------------------------------
struct SideRes {
    cudaStream_t s;
    cudaEvent_t fork, zdone;
    SideRes() {
        cudaStreamCreateWithFlags(&s, cudaStreamNonBlocking);
        cudaEventCreateWithFlags(&fork, cudaEventDisableTiming);
        cudaEventCreateWithFlags(&zdone, cudaEventDisableTiming);
    }
};
static SideRes g_side;

// ---------------------------------------------------------------------------
// zero-fill (uint4). n4 = count of uint4 elements.
// ---------------------------------------------------------------------------
__global__ void zero_fill4(float* __restrict__ p, size_t n4) {
    uint4* p4 = (uint4*)p;
    uint4 z; z.x = 0u; z.y = 0u; z.z = 0u; z.w = 0u;
    size_t i = (size_t)blockIdx.x * blockDim.x + threadIdx.x;
    size_t stride = (size_t)gridDim.x * blockDim.x;
    for (; i < n4; i += stride) p4[i] = z;
}

// ---------------------------------------------------------------------------
// Fused persistent kernel: the whole chain, 8 grid barriers.
// ---------------------------------------------------------------------------
__device__ __forceinline__ void dense_nn(const float* __restrict__ A,
                                         const float* __restrict__ B,
                                         const float* __restrict__ bias,
                                         float* __restrict__ C, bool do_relu,
                                         int gtid) {
    for (int idx = gtid; idx < NW * NF; idx += TOTALTHR) {
        int r = idx / NF, c = idx - r * NF;
        const float* Ar = A + r * NF;
        float acc = bias ? bias[c] : 0.f;
#pragma unroll 4
        for (int k = 0; k < NF; ++k) acc = fmaf(Ar[k], B[k * NF + c], acc);
        if (do_relu) acc = fmaxf(acc, 0.f);
        C[idx] = acc;
    }
}

__device__ __forceinline__ void spmm_w(const float* __restrict__ X,
                                       float* __restrict__ C, bool do_relu,
                                       int wg, int lane) {
    if (wg >= NW) return;
    int nnz = g_ccnt[wg];
    const int* cols = g_ccol + wg * CSR_CAP;
    const float* vals = g_cval + wg * CSR_CAP;
    float a0 = 0.f, a1 = 0.f, a2 = 0.f, a3 = 0.f;
    for (int q = 0; q < nnz; ++q) {
        int c = cols[q]; float v = vals[q];
        const float* Xr = X + c * NF;
        a0 = fmaf(v, Xr[lane], a0);
        a1 = fmaf(v, Xr[lane + 32], a1);
        a2 = fmaf(v, Xr[lane + 64], a2);
        if (lane < 4) a3 = fmaf(v, Xr[lane + 96], a3);
    }
    if (do_relu) {
        a0 = fmaxf(a0, 0.f); a1 = fmaxf(a1, 0.f);
        a2 = fmaxf(a2, 0.f); a3 = fmaxf(a3, 0.f);
    }
    float* Cr = C + wg * NF;
    Cr[lane] = a0; Cr[lane + 32] = a1; Cr[lane + 64] = a2;
    if (lane < 4) Cr[lane + 96] = a3;
}

#define PITCH_A 132
#define PITCH_B 68
#define FUSED_SMEM ((100 * PITCH_A + 100 * PITCH_B) * 4)   // 80000 bytes

__global__ void __launch_bounds__(NT)
fused_chain(const void* epoch, const void* epochs,
            const float* __restrict__ adj, const float* __restrict__ masks,
            const float* __restrict__ bows, const float* __restrict__ img,
            const float* __restrict__ W_g1, const float* __restrict__ W_g2,
            const float* __restrict__ W_h1, const float* __restrict__ b_h1,
            const float* __restrict__ W_h2, const float* __restrict__ b_h2,
            const float* __restrict__ W_mu2, const float* __restrict__ b_mu2,
            const float* __restrict__ W_eta2, const float* __restrict__ b_eta2,
            const float* __restrict__ W_gm2, const float* __restrict__ b_gm2,
            const float* __restrict__ w_m, const float* __restrict__ W_beta,
            const float* __restrict__ W_m1, const float* __restrict__ b_m1,
            const float* __restrict__ W_m2, const float* __restrict__ b_m2,
            float* __restrict__ oLam, float* __restrict__ oZ,
            float* __restrict__ oBeta, float* __restrict__ oGamma,
            float* __restrict__ oEta, float* __restrict__ oH) {
    extern __shared__ float sm[];
    __shared__ float sres[8];
    __shared__ int s_cnt_doc;

    const int t = threadIdx.x;
    const int lane = t & 31;
    const int wid = t >> 5;
    const int wg = blockIdx.x * (NT / 32) + wid;   // global warp id
    const int gtid = blockIdx.x * NT + t;

    // ---------------- S0: adj CSR gather (warp/row) + prune mask -----------
    if (wg < NW) {
        const float* row = adj + (size_t)wg * NW;
        int cnt = 0;
        for (int base = 0; base < NW; base += 32) {
            int c = base + lane;
            float v = (c < NW) ? row[c] : 0.f;
            unsigned m = __ballot_sync(0xffffffffu, v != 0.f);
            while (m) {
                int b = __ffs(m) - 1;
                m &= m - 1;
                float vb = __shfl_sync(0xffffffffu, v, b);
                if (lane == 0 && cnt < CSR_CAP) {
                    g_ccol[wg * CSR_CAP + cnt] = base + b;
                    g_cval[wg * CSR_CAP + cnt] = vb;
                }
                ++cnt;
            }
        }
        if (lane == 0) g_ccnt[wg] = min(cnt, CSR_CAP);
    }
    if (blockIdx.x == NBLK - 1 && t < NF) {
        float e1 = load_scalar(epoch), e2 = load_scalar(epochs);
        int j = (int)rintf((e1 / e2) * 0.3f * (float)NF);
        float wi = w_m[t];
        int rank = 0;
        for (int l = 0; l < NF; ++l) {
            float wl = w_m[l];
            if (wl < wi || (wl == wi && l < t)) ++rank;
        }
        g_wp[t] = (rank >= j) ? W_beta[t] : 0.f;
    }
    gridbar();

    // ---------------- S1: T1 = bows @ W_g1 ---------------------------------
    dense_nn(bows, W_g1, nullptr, g_T1, false, gtid);
    gridbar();

    // ---------------- S2: H1 = relu(adj @ T1) ------------------------------
    spmm_w(g_T1, g_H1, true, wg, lane);
    gridbar();

    // ---------------- S3: T2 = H1 @ W_g2 -----------------------------------
    dense_nn(g_H1, W_g2, nullptr, g_T2, false, gtid);
    gridbar();

    // ---------------- S4: H = adj @ T2 -> out ------------------------------
    spmm_w(g_T2, oH, false, wg, lane);
    gridbar();

    // ---------------- S5: E1 = relu(H@W_h1+b) ; y = H @ wp -----------------
    dense_nn(oH, W_h1, b_h1, g_E1, true, gtid);
    if (wg < NW) {
        const float* Hr = oH + (size_t)wg * NF;
        float p = Hr[lane] * g_wp[lane]
                + Hr[lane + 32] * g_wp[lane + 32]
                + Hr[lane + 64] * g_wp[lane + 64];
        if (lane < 4) p = fmaf(Hr[lane + 96], g_wp[lane + 96], p);
        p = warp_sum(p);
        if (lane == 0) g_y[wg] = p;
    }
    gridbar();

    // ---------------- S6: heli = l2norm(relu(E1@W_h2+b)) ; y-norm ----------
    {
        // cache W_h2 (+bias) in smem for this block
        for (int i = t; i < NF * NF; i += NT) sm[i] = W_h2[i];
        if (t < NF) sm[NF * NF + t] = b_h2[t];
        __syncthreads();
        if (wg < NW) {
            const float* Ar = g_E1 + (size_t)wg * NF;
            float a0 = sm[NF * NF + lane];
            float a1 = sm[NF * NF + lane + 32];
            float a2 = sm[NF * NF + lane + 64];
            float a3 = (lane < 4) ? sm[NF * NF + lane + 96] : 0.f;
            for (int k = 0; k < NF; ++k) {
                float e = Ar[k];
                const float* Wk = sm + k * NF;
                a0 = fmaf(e, Wk[lane], a0);
                a1 = fmaf(e, Wk[lane + 32], a1);
                a2 = fmaf(e, Wk[lane + 64], a2);
                if (lane < 4) a3 = fmaf(e, Wk[lane + 96], a3);
            }
            a0 = fmaxf(a0, 0.f); a1 = fmaxf(a1, 0.f);
            a2 = fmaxf(a2, 0.f); a3 = fmaxf(a3, 0.f);
            float ss = a0 * a0 + a1 * a1 + a2 * a2 + a3 * a3;
            ss = warp_sum(ss);
            float inv = 1.f / fmaxf(sqrtf(ss), 1e-12f);
            float* Cr = g_heli + (size_t)wg * NF;
            Cr[lane] = a0 * inv; Cr[lane + 32] = a1 * inv; Cr[lane + 64] = a2 * inv;
            if (lane < 4) Cr[lane + 96] = a3 * inv;
        }
        if (blockIdx.x == 0) {
            __syncthreads();
            float v = 0.f;
            for (int r = t; r < NW; r += NT) v = fmaf(g_y[r], g_y[r], v);
            sm[t] = v;
            __syncthreads();
            for (int s = 256; s; s >>= 1) {
                if (t < s) sm[t] += sm[t + s];
                __syncthreads();
            }
            if (t == 0) g_norminv = 1.f / fmaxf(sqrtf(sm[0]), 1e-12f);
        }
    }
    gridbar();

    // ---------------- S7: Z_ = relu(heli@heli^T) tiles ; beta_ write -------
    if (blockIdx.x == NBLK - 1) {
        float ninv = g_norminv;
        for (int r = t; r < NW; r += NT) oBeta[r] = g_y[r] * ninv;
    }
    if (blockIdx.x < 128) {
        float* sA = sm;                       // [100][PITCH_A] transposed
        float* sB = sm + 100 * PITCH_A;       // [100][PITCH_B]
        int rowTile = blockIdx.x >> 4;        // 0..7  (128-row tiles)
        int colTile = blockIdx.x & 15;        // 0..15 (64-col tiles)
        int rb = rowTile * 128, jb = colTile * 64;
        for (int i = t; i < 128 * NF; i += NT) {
            int rr = i / NF, kk = i - (i / NF) * NF;
            int gr = rb + rr;
            sA[kk * PITCH_A + rr] = (gr < NW) ? g_heli[(size_t)gr * NF + kk] : 0.f;
        }
        for (int i = t; i < 64 * NF; i += NT) {
            int rr = i / NF, kk = i - (i / NF) * NF;
            int gc = jb + rr;
            sB[kk * PITCH_B + rr] = (gc < NW) ? g_heli[(size_t)gc * NF + kk] : 0.f;
        }
        __syncthreads();
        int tx = t & 15, ty = t >> 4;        // ty 0..31 -> 4 rows, tx 0..15 -> 4 cols
        float acc[4][4] = {};
        for (int kk = 0; kk < NF; ++kk) {
            float4 a = *(const float4*)&sA[kk * PITCH_A + ty * 4];
            float4 b = *(const float4*)&sB[kk * PITCH_B + tx * 4];
            float av[4] = {a.x, a.y, a.z, a.w};
            float bv[4] = {b.x, b.y, b.z, b.w};
#pragma unroll
            for (int r = 0; r < 4; ++r)
#pragma unroll
                for (int c = 0; c < 4; ++c)
                    acc[r][c] = fmaf(av[r], bv[c], acc[r][c]);
        }
#pragma unroll
        for (int r = 0; r < 4; ++r) {
            int gr = rb + ty * 4 + r;
            if (gr >= NW) continue;
#pragma unroll
            for (int c = 0; c < 4; ++c) {
                int gc = jb + tx * 4 + c;
                if (gc >= NW) continue;
                oZ[(size_t)gr * NW + gc] = fmaxf(acc[r][c], 0.f);
            }
        }
    }
    gridbar();

    // ---------------- S8: per-doc epilogue (blocks 0..99) ------------------
    if (blockIdx.x < ND) {
        int d = blockIdx.x;
        int* cols = (int*)sm;          // [160]
        float* red = sm + 160;         // [512]
        float* hp = red + NT;          // [128]
        float* simg = hp + 128;        // [512]

        if (wid == 0) {
            const float* mrow = masks + (size_t)d * NW;
            int cnt = 0;
            for (int base = 0; base < NW; base += 32) {
                int c = base + lane;
                float v = (c < NW) ? mrow[c] : 0.f;
                unsigned m = __ballot_sync(0xffffffffu, v != 0.f);
                while (m) {
                    int b = __ffs(m) - 1;
                    m &= m - 1;
                    if (lane == 0 && cnt < 160) cols[cnt] = base + b;
                    ++cnt;
                }
            }
            if (lane == 0) s_cnt_doc = min(cnt, 160);
        }
        __syncthreads();
        int cnt = s_cnt_doc;
        float fk = (float)cnt;

        // H_p row + s row
        float sv = 0.f;
        if (t < NF) {
            float hpv = 0.f;
            for (int q = 0; q < cnt; ++q) {
                int c = cols[q];
                hpv += oH[(size_t)c * NF + t];
                sv += g_heli[(size_t)c * NF + t];
            }
            hp[t] = hpv / fmaxf(fk, 1.f);
        }
        red[t] = (t < NF) ? sv * sv : 0.f;
        __syncthreads();
        for (int s = 256; s; s >>= 1) { if (t < s) red[t] += red[t + s]; __syncthreads(); }
        if (t == 0) sres[0] = red[0];   // ss
        __syncthreads();

        // beta_doc
        red[t] = (t < cnt) ? oBeta[cols[t]] : 0.f;
        __syncthreads();
        for (int s = 256; s; s >>= 1) { if (t < s) red[t] += red[t + s]; __syncthreads(); }
        if (t == 0) sres[1] = red[0];
        __syncthreads();

        // mu / eta / gamma
        float hpt = (t < NF) ? hp[t] : 0.f;
        red[t] = (t < NF) ? hpt * W_mu2[t] : 0.f;
        __syncthreads();
        for (int s = 256; s; s >>= 1) { if (t < s) red[t] += red[t + s]; __syncthreads(); }
        if (t == 0) sres[2] = fmaxf(red[0] + b_mu2[0], 0.f);
        __syncthreads();
        red[t] = (t < NF) ? hpt * W_eta2[t] : 0.f;
        __syncthreads();
        for (int s = 256; s; s >>= 1) { if (t < s) red[t] += red[t + s]; __syncthreads(); }
        if (t == 0) sres[3] = fmaxf(red[0] + b_eta2[0], 0.f);
        __syncthreads();
        red[t] = (t < NF) ? hpt * W_gm2[t] : 0.f;
        __syncthreads();
        for (int s = 256; s; s >>= 1) { if (t < s) red[t] += red[t + s]; __syncthreads(); }
        if (t == 0) sres[4] = fmaxf(red[0] + b_gm2[0], 0.f);
        __syncthreads();

        // image MLP
        for (int k = t; k < TIw; k += NT) simg[k] = img[(size_t)d * TIw + k];
        __syncthreads();
        float contrib = 0.f;
        if (t < HDw) {
            float hv = b_m1[t];
            for (int k = 0; k < TIw; ++k) hv = fmaf(simg[k], W_m1[(size_t)k * HDw + t], hv);
            contrib = fmaxf(hv, 0.f) * W_m2[t];
        }
        red[t] = contrib;
        __syncthreads();
        for (int s = 256; s; s >>= 1) { if (t < s) red[t] += red[t + s]; __syncthreads(); }

        if (t == 0) {
            float li = red[0] + b_m2[0];
            float ss = sres[0], bd = sres[1], mu = sres[2], eta = sres[3], gm = sres[4];
            float Z = fmaxf(0.5f * (ss - fk), 0.f);
            float inner = mu + bd + eta * expf(-gm * Z);
            float lt = 1.f / (1.f + expf(-inner));
            oLam[d] = 1.f / (1.f + expf(-(lt + li)));
            oEta[d] = eta;
            oGamma[d] = gm;
            g_kc[d] = fk;
        }
    }
}

// ---------------------------------------------------------------------------
// Z_event patch (background already zero-filled)
// ---------------------------------------------------------------------------
__global__ void zevent_fill(const float* __restrict__ Zmat, float* __restrict__ ze) {
    int d = blockIdx.x;
    int kd = (int)(g_kc[d] + 0.5f);
    if (kd > NW) kd = NW;
    if (kd <= 0) return;
    int total = kd * kd;
    float* zed = ze + (size_t)d * NW * NW;
    for (int idx = threadIdx.x; idx < total; idx += blockDim.x) {
        int i = idx / kd;
        int j = idx - i * kd;
        float v = 0.f;
        if (i != j) {
            float tt = 2.f - 2.f * Zmat[(size_t)i * NW + j];
            v = expf(-tt * tt);
        }
        zed[(size_t)i * NW + j] = v;
    }
}

// ---------------------------------------------------------------------------
// Host launch
// ---------------------------------------------------------------------------
extern "C" void kernel_launch(void* const* d_in, const int* in_sizes, int n_in,
                              void* d_out, int out_size) {
    (void)in_sizes; (void)n_in; (void)out_size;
    const void*  epoch  = d_in[0];
    const void*  epochs = d_in[1];
    const float* adj    = (const float*)d_in[2];
    const float* masks  = (const float*)d_in[3];
    const float* bows   = (const float*)d_in[4];
    const float* img    = (const float*)d_in[5];
    const float* W_g1   = (const float*)d_in[6];
    const float* W_g2   = (const float*)d_in[7];
    const float* W_h1   = (const float*)d_in[8];
    const float* b_h1   = (const float*)d_in[9];
    const float* W_h2   = (const float*)d_in[10];
    const float* b_h2   = (const float*)d_in[11];
    const float* W_mu2  = (const float*)d_in[12];
    const float* b_mu2  = (const float*)d_in[13];
    const float* W_eta2 = (const float*)d_in[14];
    const float* b_eta2 = (const float*)d_in[15];
    const float* W_gm2  = (const float*)d_in[16];
    const float* b_gm2  = (const float*)d_in[17];
    const float* w_m    = (const float*)d_in[18];
    const float* W_beta = (const float*)d_in[19];
    const float* W_m1   = (const float*)d_in[20];
    const float* b_m1   = (const float*)d_in[21];
    const float* W_m2   = (const float*)d_in[22];
    const float* b_m2   = (const float*)d_in[23];

    float* out = (float*)d_out;
    float* oLam   = out + OFF_LAM;
    float* oZ     = out + OFF_ZMAT;
    float* oBeta  = out + OFF_BETA;
    float* oGamma = out + OFF_GAMMA;
    float* oEta   = out + OFF_ETA;
    float* oZev   = out + OFF_ZEV;
    float* oH     = out + OFF_H;

    static bool attr_set = false;
    if (!attr_set) {
        cudaFuncSetAttribute(fused_chain, cudaFuncAttributeMaxDynamicSharedMemorySize,
                             FUSED_SMEM);
        attr_set = true;
    }

    // fork: zero-fill the 400MB Z_event region on the side stream
    cudaEventRecord(g_side.fork, 0);
    cudaStreamWaitEvent(g_side.s, g_side.fork, 0);
    zero_fill4<<<4096, 256, 0, g_side.s>>>(oZev, (size_t)ND * NW * NW / 4);
    cudaEventRecord(g_side.zdone, g_side.s);

    // main: single fused persistent kernel for the entire chain
    fused_chain<<<NBLK, NT, FUSED_SMEM>>>(
        epoch, epochs, adj, masks, bows, img,
        W_g1, W_g2, W_h1, b_h1, W_h2, b_h2,
        W_mu2, b_mu2, W_eta2, b_eta2, W_gm2, b_gm2,
        w_m, W_beta, W_m1, b_m1, W_m2, b_m2,
        oLam, oZ, oBeta, oGamma, oEta, oH);

    // join: patch Z_event nonzero blocks
    cudaStreamWaitEvent(0, g_side.zdone, 0);
    zevent_fill<<<ND, 256>>>(oZ, oZev);
}

// round 4
// speedup vs baseline: 1.0859x; 1.0859x over previous
#include <cuda_runtime.h>
#include <cuda_bf16.h>
#include <math.h>
#include <stdint.h>

// ---------------------------------------------------------------------------
// Problem constants
// ---------------------------------------------------------------------------
#define NW 1000   // words
#define ND 100    // docs
#define NF 100    // feature dim
#define TIw 512
#define HDw 128

#define NBLK 148
#define NT 512
#define TOTALTHR (NBLK * NT)

// Output layout (concatenated f32)
#define OFF_LAM   0
#define OFF_ZMAT  100
#define OFF_BETA  1000100
#define OFF_GAMMA 1001100
#define OFF_ETA   1001200
#define OFF_ZEV   1001300
#define OFF_H     101001300

// ---------------------------------------------------------------------------
// Device scratch (single-assignment per stage -> no stale-L1 hazards)
// ---------------------------------------------------------------------------
__device__ float g_T1[NW * NF];
__device__ float g_H1[NW * NF];
__device__ float g_T2[NW * NF];
__device__ float g_E1[NW * NF];
__device__ float g_heli[NW * NF];
__device__ float g_y[NW];
__device__ float g_wp[NF];
__device__ int   g_kci[ND];
__device__ float g_norminv;

#define CSR_CAP 96
__device__ int   g_ccnt[NW];
__device__ int   g_ccol[NW * CSR_CAP];
__device__ float g_cval[NW * CSR_CAP];

// grid barrier state
__device__ unsigned g_barcnt = 0;
__device__ volatile unsigned g_bargen = 0;

__device__ __forceinline__ void gridbar() {
    __syncthreads();
    if (threadIdx.x == 0) {
        __threadfence();
        unsigned g = g_bargen;
        if (atomicAdd(&g_barcnt, 1u) == NBLK - 1) {
            g_barcnt = 0;
            __threadfence();
            g_bargen = g + 1;
        } else {
            while (g_bargen == g) { __nanosleep(128); }
        }
    }
    __syncthreads();
}

__device__ __forceinline__ float warp_sum(float v) {
#pragma unroll
    for (int o = 16; o; o >>= 1) v += __shfl_xor_sync(0xffffffffu, v, o);
    return v;
}

__device__ __forceinline__ float load_scalar(const void* p) {
    int v = *(const int*)p;
    if (v >= 0 && v <= 1000000) return (float)v;
    return *(const float*)p;
}

// ---------------------------------------------------------------------------
// helpers
// ---------------------------------------------------------------------------
__device__ __forceinline__ void dense_nn(const float* __restrict__ A,
                                         const float* __restrict__ B,
                                         const float* __restrict__ bias,
                                         float* __restrict__ C, bool do_relu,
                                         int gtid) {
    for (int idx = gtid; idx < NW * NF; idx += TOTALTHR) {
        int r = idx / NF, c = idx - r * NF;
        const float* Ar = A + r * NF;
        float acc = bias ? bias[c] : 0.f;
#pragma unroll 4
        for (int k = 0; k < NF; ++k) acc = fmaf(Ar[k], B[k * NF + c], acc);
        if (do_relu) acc = fmaxf(acc, 0.f);
        C[idx] = acc;
    }
}

__device__ __forceinline__ void spmm_w(const float* __restrict__ X,
                                       float* __restrict__ C, bool do_relu,
                                       int wg, int lane) {
    if (wg >= NW) return;
    int nnz = g_ccnt[wg];
    const int* cols = g_ccol + wg * CSR_CAP;
    const float* vals = g_cval + wg * CSR_CAP;
    float a0 = 0.f, a1 = 0.f, a2 = 0.f, a3 = 0.f;
    for (int q = 0; q < nnz; ++q) {
        int c = cols[q]; float v = vals[q];
        const float* Xr = X + c * NF;
        a0 = fmaf(v, Xr[lane], a0);
        a1 = fmaf(v, Xr[lane + 32], a1);
        a2 = fmaf(v, Xr[lane + 64], a2);
        if (lane < 4) a3 = fmaf(v, Xr[lane + 96], a3);
    }
    if (do_relu) {
        a0 = fmaxf(a0, 0.f); a1 = fmaxf(a1, 0.f);
        a2 = fmaxf(a2, 0.f); a3 = fmaxf(a3, 0.f);
    }
    float* Cr = C + wg * NF;
    Cr[lane] = a0; Cr[lane + 32] = a1; Cr[lane + 64] = a2;
    if (lane < 4) Cr[lane + 96] = a3;
}

#define PITCH_A 132
#define PITCH_B 68
#define FUSED_SMEM ((100 * PITCH_A + 100 * PITCH_B) * 4)   // 80000 bytes

// ---------------------------------------------------------------------------
// ONE persistent kernel: entire chain + full Z_event streaming write.
// ---------------------------------------------------------------------------
__global__ void __launch_bounds__(NT)
fused_all(const void* epoch, const void* epochs,
          const float* __restrict__ adj, const float* __restrict__ masks,
          const float* __restrict__ bows, const float* __restrict__ img,
          const float* __restrict__ W_g1, const float* __restrict__ W_g2,
          const float* __restrict__ W_h1, const float* __restrict__ b_h1,
          const float* __restrict__ W_h2, const float* __restrict__ b_h2,
          const float* __restrict__ W_mu2, const float* __restrict__ b_mu2,
          const float* __restrict__ W_eta2, const float* __restrict__ b_eta2,
          const float* __restrict__ W_gm2, const float* __restrict__ b_gm2,
          const float* __restrict__ w_m, const float* __restrict__ W_beta,
          const float* __restrict__ W_m1, const float* __restrict__ b_m1,
          const float* __restrict__ W_m2, const float* __restrict__ b_m2,
          float* __restrict__ oLam, float* __restrict__ oZ,
          float* __restrict__ oBeta, float* __restrict__ oGamma,
          float* __restrict__ oEta, float* __restrict__ oZev,
          float* __restrict__ oH) {
    extern __shared__ float sm[];
    __shared__ float sres[8];
    __shared__ int s_cnt_doc;

    const int t = threadIdx.x;
    const int lane = t & 31;
    const int wid = t >> 5;
    const int wg = blockIdx.x * (NT / 32) + wid;   // global warp id
    const int gtid = blockIdx.x * NT + t;

    // ---- S0+S1: adj CSR gather (warp/row), prune mask, T1 = bows @ W_g1 ----
    if (wg < NW) {
        const float* row = adj + (size_t)wg * NW;
        int cnt = 0;
        for (int base = 0; base < NW; base += 32) {
            int c = base + lane;
            float v = (c < NW) ? row[c] : 0.f;
            unsigned m = __ballot_sync(0xffffffffu, v != 0.f);
            while (m) {
                int b = __ffs(m) - 1;
                m &= m - 1;
                float vb = __shfl_sync(0xffffffffu, v, b);
                if (lane == 0 && cnt < CSR_CAP) {
                    g_ccol[wg * CSR_CAP + cnt] = base + b;
                    g_cval[wg * CSR_CAP + cnt] = vb;
                }
                ++cnt;
            }
        }
        if (lane == 0) g_ccnt[wg] = min(cnt, CSR_CAP);
    }
    if (blockIdx.x == NBLK - 1 && t < NF) {
        float e1 = load_scalar(epoch), e2 = load_scalar(epochs);
        int j = (int)rintf((e1 / e2) * 0.3f * (float)NF);
        float wi = w_m[t];
        int rank = 0;
        for (int l = 0; l < NF; ++l) {
            float wl = w_m[l];
            if (wl < wi || (wl == wi && l < t)) ++rank;
        }
        g_wp[t] = (rank >= j) ? W_beta[t] : 0.f;
    }
    dense_nn(bows, W_g1, nullptr, g_T1, false, gtid);
    gridbar();

    // ---- S2: H1 = relu(adj @ T1) ------------------------------------------
    spmm_w(g_T1, g_H1, true, wg, lane);
    gridbar();

    // ---- S3: T2 = H1 @ W_g2 -------------------------------------------------
    dense_nn(g_H1, W_g2, nullptr, g_T2, false, gtid);
    gridbar();

    // ---- S4: H = adj @ T2 -> out --------------------------------------------
    spmm_w(g_T2, oH, false, wg, lane);
    gridbar();

    // ---- S5: E1 = relu(H@W_h1+b) ; y = H @ wp -------------------------------
    dense_nn(oH, W_h1, b_h1, g_E1, true, gtid);
    if (wg < NW) {
        const float* Hr = oH + (size_t)wg * NF;
        float p = Hr[lane] * g_wp[lane]
                + Hr[lane + 32] * g_wp[lane + 32]
                + Hr[lane + 64] * g_wp[lane + 64];
        if (lane < 4) p = fmaf(Hr[lane + 96], g_wp[lane + 96], p);
        p = warp_sum(p);
        if (lane == 0) g_y[wg] = p;
    }
    gridbar();

    // ---- S6: heli = l2norm(relu(E1@W_h2+b)) ; ||y|| -------------------------
    {
        for (int i = t; i < NF * NF; i += NT) sm[i] = W_h2[i];
        if (t < NF) sm[NF * NF + t] = b_h2[t];
        __syncthreads();
        if (wg < NW) {
            const float* Ar = g_E1 + (size_t)wg * NF;
            float a0 = sm[NF * NF + lane];
            float a1 = sm[NF * NF + lane + 32];
            float a2 = sm[NF * NF + lane + 64];
            float a3 = (lane < 4) ? sm[NF * NF + lane + 96] : 0.f;
            for (int k = 0; k < NF; ++k) {
                float e = Ar[k];
                const float* Wk = sm + k * NF;
                a0 = fmaf(e, Wk[lane], a0);
                a1 = fmaf(e, Wk[lane + 32], a1);
                a2 = fmaf(e, Wk[lane + 64], a2);
                if (lane < 4) a3 = fmaf(e, Wk[lane + 96], a3);
            }
            a0 = fmaxf(a0, 0.f); a1 = fmaxf(a1, 0.f);
            a2 = fmaxf(a2, 0.f); a3 = fmaxf(a3, 0.f);
            float ss = a0 * a0 + a1 * a1 + a2 * a2 + a3 * a3;
            ss = warp_sum(ss);
            float inv = 1.f / fmaxf(sqrtf(ss), 1e-12f);
            float* Cr = g_heli + (size_t)wg * NF;
            Cr[lane] = a0 * inv; Cr[lane + 32] = a1 * inv; Cr[lane + 64] = a2 * inv;
            if (lane < 4) Cr[lane + 96] = a3 * inv;
        }
        if (blockIdx.x == 0) {
            __syncthreads();
            float v = 0.f;
            for (int r = t; r < NW; r += NT) v = fmaf(g_y[r], g_y[r], v);
            sm[t] = v;
            __syncthreads();
            for (int s = 256; s; s >>= 1) {
                if (t < s) sm[t] += sm[t + s];
                __syncthreads();
            }
            if (t == 0) g_norminv = 1.f / fmaxf(sqrtf(sm[0]), 1e-12f);
        }
    }
    gridbar();

    // ---- S7: Z_ = relu(heli@heli^T) tiles ; beta_ write ---------------------
    if (blockIdx.x == NBLK - 1) {
        float ninv = g_norminv;
        for (int r = t; r < NW; r += NT) oBeta[r] = g_y[r] * ninv;
    }
    if (blockIdx.x < 128) {
        float* sA = sm;                       // [100][PITCH_A] transposed
        float* sB = sm + 100 * PITCH_A;       // [100][PITCH_B]
        int rowTile = blockIdx.x >> 4;
        int colTile = blockIdx.x & 15;
        int rb = rowTile * 128, jb = colTile * 64;
        for (int i = t; i < 128 * NF; i += NT) {
            int rr = i / NF, kk = i - (i / NF) * NF;
            int gr = rb + rr;
            sA[kk * PITCH_A + rr] = (gr < NW) ? g_heli[(size_t)gr * NF + kk] : 0.f;
        }
        for (int i = t; i < 64 * NF; i += NT) {
            int rr = i / NF, kk = i - (i / NF) * NF;
            int gc = jb + rr;
            sB[kk * PITCH_B + rr] = (gc < NW) ? g_heli[(size_t)gc * NF + kk] : 0.f;
        }
        __syncthreads();
        int tx = t & 15, ty = t >> 4;
        float acc[4][4] = {};
        for (int kk = 0; kk < NF; ++kk) {
            float4 a = *(const float4*)&sA[kk * PITCH_A + ty * 4];
            float4 b = *(const float4*)&sB[kk * PITCH_B + tx * 4];
            float av[4] = {a.x, a.y, a.z, a.w};
            float bv[4] = {b.x, b.y, b.z, b.w};
#pragma unroll
            for (int r = 0; r < 4; ++r)
#pragma unroll
                for (int c = 0; c < 4; ++c)
                    acc[r][c] = fmaf(av[r], bv[c], acc[r][c]);
        }
#pragma unroll
        for (int r = 0; r < 4; ++r) {
            int gr = rb + ty * 4 + r;
            if (gr >= NW) continue;
#pragma unroll
            for (int c = 0; c < 4; ++c) {
                int gc = jb + tx * 4 + c;
                if (gc >= NW) continue;
                oZ[(size_t)gr * NW + gc] = fmaxf(acc[r][c], 0.f);
            }
        }
    }
    gridbar();

    // ---- S8: per-doc epilogue (blocks 0..99) --------------------------------
    if (blockIdx.x < ND) {
        int d = blockIdx.x;
        int* cols = (int*)sm;          // [160]
        float* red = sm + 160;         // [512]
        float* hp = red + NT;          // [128]
        float* simg = hp + 128;        // [512]

        if (wid == 0) {
            const float* mrow = masks + (size_t)d * NW;
            int cnt = 0;
            for (int base = 0; base < NW; base += 32) {
                int c = base + lane;
                float v = (c < NW) ? mrow[c] : 0.f;
                unsigned m = __ballot_sync(0xffffffffu, v != 0.f);
                while (m) {
                    int b = __ffs(m) - 1;
                    m &= m - 1;
                    if (lane == 0 && cnt < 160) cols[cnt] = base + b;
                    ++cnt;
                }
            }
            if (lane == 0) s_cnt_doc = min(cnt, 160);
        }
        __syncthreads();
        int cnt = s_cnt_doc;
        float fk = (float)cnt;

        float sv = 0.f;
        if (t < NF) {
            float hpv = 0.f;
            for (int q = 0; q < cnt; ++q) {
                int c = cols[q];
                hpv += oH[(size_t)c * NF + t];
                sv += g_heli[(size_t)c * NF + t];
            }
            hp[t] = hpv / fmaxf(fk, 1.f);
        }
        red[t] = (t < NF) ? sv * sv : 0.f;
        __syncthreads();
        for (int s = 256; s; s >>= 1) { if (t < s) red[t] += red[t + s]; __syncthreads(); }
        if (t == 0) sres[0] = red[0];
        __syncthreads();

        red[t] = (t < cnt) ? oBeta[cols[t]] : 0.f;
        __syncthreads();
        for (int s = 256; s; s >>= 1) { if (t < s) red[t] += red[t + s]; __syncthreads(); }
        if (t == 0) sres[1] = red[0];
        __syncthreads();

        float hpt = (t < NF) ? hp[t] : 0.f;
        red[t] = (t < NF) ? hpt * W_mu2[t] : 0.f;
        __syncthreads();
        for (int s = 256; s; s >>= 1) { if (t < s) red[t] += red[t + s]; __syncthreads(); }
        if (t == 0) sres[2] = fmaxf(red[0] + b_mu2[0], 0.f);
        __syncthreads();
        red[t] = (t < NF) ? hpt * W_eta2[t] : 0.f;
        __syncthreads();
        for (int s = 256; s; s >>= 1) { if (t < s) red[t] += red[t + s]; __syncthreads(); }
        if (t == 0) sres[3] = fmaxf(red[0] + b_eta2[0], 0.f);
        __syncthreads();
        red[t] = (t < NF) ? hpt * W_gm2[t] : 0.f;
        __syncthreads();
        for (int s = 256; s; s >>= 1) { if (t < s) red[t] += red[t + s]; __syncthreads(); }
        if (t == 0) sres[4] = fmaxf(red[0] + b_gm2[0], 0.f);
        __syncthreads();

        for (int k = t; k < TIw; k += NT) simg[k] = img[(size_t)d * TIw + k];
        __syncthreads();
        float contrib = 0.f;
        if (t < HDw) {
            float hv = b_m1[t];
            for (int k = 0; k < TIw; ++k) hv = fmaf(simg[k], W_m1[(size_t)k * HDw + t], hv);
            contrib = fmaxf(hv, 0.f) * W_m2[t];
        }
        red[t] = contrib;
        __syncthreads();
        for (int s = 256; s; s >>= 1) { if (t < s) red[t] += red[t + s]; __syncthreads(); }

        if (t == 0) {
            float li = red[0] + b_m2[0];
            float ss = sres[0], bd = sres[1], mu = sres[2], eta = sres[3], gm = sres[4];
            float Z = fmaxf(0.5f * (ss - fk), 0.f);
            float inner = mu + bd + eta * expf(-gm * Z);
            float lt = 1.f / (1.f + expf(-inner));
            oLam[d] = 1.f / (1.f + expf(-(lt + li)));
            oEta[d] = eta;
            oGamma[d] = gm;
            g_kci[d] = cnt;
        }
    }
    gridbar();

    // ---- S9: Z_event full streaming write (zeros + computed blocks) --------
    {
        const unsigned total4 = (unsigned)((size_t)ND * NW * NW / 4);  // 25,000,000
        uint4 z; z.x = 0u; z.y = 0u; z.z = 0u; z.w = 0u;
        uint4* base4 = (uint4*)oZev;
        for (unsigned g = (unsigned)gtid; g < total4; g += (unsigned)TOTALTHR) {
            unsigned d = g / 250000u;
            unsigned rem = g - d * 250000u;
            unsigned i = rem / 250u;
            unsigned j4 = (rem - i * 250u) << 2;
            int kd = g_kci[d];
            if ((int)i < kd && (int)j4 < kd) {
                const float* zr = oZ + (size_t)i * NW + j4;
                float4 v;
                float* vv = (float*)&v;
#pragma unroll
                for (int c = 0; c < 4; ++c) {
                    int j = (int)j4 + c;
                    float val = 0.f;
                    if (j < kd && j != (int)i) {
                        float tt = 2.f - 2.f * zr[c];
                        val = expf(-tt * tt);
                    }
                    vv[c] = val;
                }
                *(float4*)(base4 + g) = v;
            } else {
                base4[g] = z;
            }
        }
    }
}

// ---------------------------------------------------------------------------
// Host launch: ONE kernel.
// ---------------------------------------------------------------------------
extern "C" void kernel_launch(void* const* d_in, const int* in_sizes, int n_in,
                              void* d_out, int out_size) {
    (void)in_sizes; (void)n_in; (void)out_size;
    const void*  epoch  = d_in[0];
    const void*  epochs = d_in[1];
    const float* adj    = (const float*)d_in[2];
    const float* masks  = (const float*)d_in[3];
    const float* bows   = (const float*)d_in[4];
    const float* img    = (const float*)d_in[5];
    const float* W_g1   = (const float*)d_in[6];
    const float* W_g2   = (const float*)d_in[7];
    const float* W_h1   = (const float*)d_in[8];
    const float* b_h1   = (const float*)d_in[9];
    const float* W_h2   = (const float*)d_in[10];
    const float* b_h2   = (const float*)d_in[11];
    const float* W_mu2  = (const float*)d_in[12];
    const float* b_mu2  = (const float*)d_in[13];
    const float* W_eta2 = (const float*)d_in[14];
    const float* b_eta2 = (const float*)d_in[15];
    const float* W_gm2  = (const float*)d_in[16];
    const float* b_gm2  = (const float*)d_in[17];
    const float* w_m    = (const float*)d_in[18];
    const float* W_beta = (const float*)d_in[19];
    const float* W_m1   = (const float*)d_in[20];
    const float* b_m1   = (const float*)d_in[21];
    const float* W_m2   = (const float*)d_in[22];
    const float* b_m2   = (const float*)d_in[23];

    float* out = (float*)d_out;

    cudaFuncSetAttribute(fused_all, cudaFuncAttributeMaxDynamicSharedMemorySize,
                         FUSED_SMEM);

    fused_all<<<NBLK, NT, FUSED_SMEM>>>(
        epoch, epochs, adj, masks, bows, img,
        W_g1, W_g2, W_h1, b_h1, W_h2, b_h2,
        W_mu2, b_mu2, W_eta2, b_eta2, W_gm2, b_gm2,
        w_m, W_beta, W_m1, b_m1, W_m2, b_m2,
        out + OFF_LAM, out + OFF_ZMAT, out + OFF_BETA,
        out + OFF_GAMMA, out + OFF_ETA, out + OFF_ZEV, out + OFF_H);
}